// round 5
// baseline (speedup 1.0000x reference)
#include <cuda_runtime.h>
#include <cuda_bf16.h>

// TrafficAugmentation [B=2048, S=4096] -> [B, S, 1] f32.
//
// Per row (one block, NT=256):
//  P0: stage x, dly into SMEM (float4); prefetch rtt row into L1.
//  P1: per-position delay countdown as a flat restart loop: each lane owns
//      16 positions, walks them back-to-back in 4-wide batches (exact
//      sequential fsub chain) -> snxt[s] (u16 burst-end | kill).
//  P2: per 32-chunk backward scan -> exit[s] (aliases dead dly buffer).
//  P3: serial top walk (<=128 hops, branchy) -> chain entry per chunk.
//  P4: per-chunk output-slot counts (128 threads; vectorized exact sums).
//  P5: warp-shfl exclusive scan of chunk counts.
//  P6: per-chunk emission of MSS runs + remainders (dense, disjoint);
//      spare thread publishes grand total.
//  P7: store outrow[i] for i < total, else 0 (burst ranges tile [0,total)).

#define SS     4096
#define CHUNK  32
#define NCHUNK (SS / CHUNK)     // 128
#define MSSF   1448.0f
#define KILL16 0x8000u
#define NT     256

// Exact index-ordered sum of sx[s0..e1) via aligned float4 loads;
// fp op order identical to the scalar loop (predicated edges).
__device__ __forceinline__ float burst_sum(const float* __restrict__ sxp,
                                           int s0, int e1)
{
    const float4* v4 = (const float4*)sxp;
    float buf = 0.0f;
    for (int jb = (s0 & ~3); jb < e1; jb += 4) {
        float4 v = v4[jb >> 2];
        if (jb     >= s0)                 buf = __fadd_rn(buf, v.x);
        if (jb + 1 >= s0 && jb + 1 < e1)  buf = __fadd_rn(buf, v.y);
        if (jb + 2 >= s0 && jb + 2 < e1)  buf = __fadd_rn(buf, v.z);
        if (jb + 3 >= s0 && jb + 3 < e1)  buf = __fadd_rn(buf, v.w);
    }
    return buf;
}

__global__ __launch_bounds__(NT, 5)
void traffic_kernel(const float* __restrict__ x,
                    const float* __restrict__ dly,
                    const float* __restrict__ rtt,
                    float* __restrict__ out)
{
    __shared__ __align__(16) float sx[SS + 4];   // x row + 0 pads
    __shared__ __align__(16) float sd[SS + 4];   // dly row + 1e30 pads; later:
                                                 //  P2/P3: exit table (u16)
                                                 //  P6/P7: output row (f32)
    __shared__ unsigned short snxt[SS];          // burst-end | kill
    __shared__ unsigned short senter[NCHUNK];    // chain entry per chunk
    __shared__ int swsum[NCHUNK / 32];           // per-warp count totals
    __shared__ int s_total;                      // grand output count

    const int row  = blockIdx.x;
    const size_t base = (size_t)row * SS;
    const int tid = threadIdx.x;

    // ---- P0: stage inputs; warm rtt row in L1 ----------------------------
    if (tid < NCHUNK)            // 128 lines x 128B = whole rtt row
        asm volatile("prefetch.global.L1 [%0];"
                     :: "l"(rtt + base + (size_t)tid * 32));
    {
        const float4* x4 = (const float4*)(x + base);
        const float4* d4 = (const float4*)(dly + base);
        float4* sx4 = (float4*)sx;
        float4* sd4 = (float4*)sd;
        #pragma unroll
        for (int i = tid; i < SS / 4; i += NT) { sx4[i] = x4[i]; sd4[i] = d4[i]; }
        if (tid < 4) { sx[SS + tid] = 0.0f; sd[SS + tid] = 1e30f; }
    }
    __syncthreads();

    // ---- P1: burst ends, flat restart loop (16 positions per lane) -------
    {
        int k = 0;
        int s = tid;
        int j = s;
        bool alive = (sx[s] > 0.0f);
        float r = __ldg(rtt + base + s);
        for (;;) {
            int e = 0;                       // 0=continue, >0 end+1, -1 kill
            if (!alive) {
                e = -1;
            } else {
                // 1e30 pads at sd[SS..SS+3] force termination past SS
                float d0 = sd[j], d1 = sd[j+1], d2 = sd[j+2], d3 = sd[j+3];
                r = __fsub_rn(r, d0);        // exact sequential chain
                if (r <= 0.0f) e = j + 1; else {
                r = __fsub_rn(r, d1);
                if (r <= 0.0f) e = j + 2; else {
                r = __fsub_rn(r, d2);
                if (r <= 0.0f) e = j + 3; else {
                r = __fsub_rn(r, d3);
                if (r <= 0.0f) e = j + 4; } } }
            }
            if (e == 0) { j += 4; continue; }
            snxt[s] = (e < 0) ? (unsigned short)KILL16
                              : (unsigned short)(e < SS ? e : SS);
            if (++k == SS / NT) break;
            s = tid + k * NT;                // restart on next owned position
            j = s;
            alive = (sx[s] > 0.0f);
            r = __ldg(rtt + base + s);       // L1-warm (prefetched)
        }
    }
    __syncthreads();

    // ---- P2: per-chunk exit table (backward; nxt strictly increasing) ----
    unsigned short* sexit = (unsigned short*)sd;       // dly is dead
    if (tid < NCHUNK) {
        const int c = tid;
        const int end = (c + 1) * CHUNK;
        for (int s = end - 1; s >= c * CHUNK; s--) {
            unsigned short w = snxt[s];
            unsigned short e;
            if (w & KILL16)         e = (unsigned short)SS;  // chain dies
            else if ((int)w >= end) e = w;                   // leaves chunk
            else                    e = sexit[w];            // compose
            sexit[s] = e;
        }
    }
    __syncthreads();

    // ---- P3: serial top walk (<= NCHUNK hops, branchy: untaken = cheap) --
    if (tid == 0) {
        int pos = 0;
        #pragma unroll 4
        for (int c = 0; c < NCHUNK; c++) {
            senter[c] = (unsigned short)pos;
            if (pos < (c + 1) * CHUNK) pos = sexit[pos];
        }
    }
    __syncthreads();

    // ---- P4: per-chunk output-slot count ---------------------------------
    int cnt = 0;
    if (tid < NCHUNK) {
        const int end = (tid + 1) * CHUNK;
        int s = senter[tid];
        while (s < end) {
            unsigned short w = snxt[s];
            if (w & KILL16) break;
            const int e1 = (int)w;
            float buf = burst_sum(sx, s, e1);
            int nf = (int)ceilf(__fdiv_rn(buf, MSSF)) - 1;
            if (nf < 0) nf = 0;
            float rem = __fsub_rn(buf, __fmul_rn((float)nf, MSSF));
            cnt += nf + (rem > 0.0f ? 1 : 0);
            s = e1;
        }
    }
    __syncthreads();   // sexit dead after this point; sd becomes outrow

    // ---- P5: warp-shfl exclusive scan of chunk counts --------------------
    int inc = cnt;
    if (tid < NCHUNK) {
        const int lane = tid & 31;
        #pragma unroll
        for (int d = 1; d < 32; d <<= 1) {
            int n = __shfl_up_sync(0xffffffffu, inc, d);
            if (lane >= d) inc += n;
        }
        if (lane == 31) swsum[tid >> 5] = inc;          // warp inclusive total
    }
    __syncthreads();

    // ---- P6: dense per-chunk emission + grand total ----------------------
    float* outrow = sd;
    if (tid < NCHUNK) {
        int o = inc - cnt;                              // exclusive within warp
        #pragma unroll
        for (int k = 0; k < NCHUNK / 32; k++)
            if (k < (tid >> 5)) o += swsum[k];
        const int end = (tid + 1) * CHUNK;
        int s = senter[tid];
        while (s < end) {
            unsigned short w = snxt[s];
            if (w & KILL16) break;
            const int e1 = (int)w;
            float buf = burst_sum(sx, s, e1);           // identical fp order
            int nf = (int)ceilf(__fdiv_rn(buf, MSSF)) - 1;
            if (nf < 0) nf = 0;
            float rem = __fsub_rn(buf, __fmul_rn((float)nf, MSSF));
            int lim = nf;
            if (o + lim > SS) lim = SS - o;             // truncation at row end
            for (int k = 0; k < lim; k++) outrow[o + k] = MSSF;
            if (rem > 0.0f && o + nf < SS) outrow[o + nf] = rem;
            o += nf + (rem > 0.0f ? 1 : 0);             // slots [o,o+count) dense
            s = e1;
        }
    } else if (tid == NCHUNK) {
        int t = 0;
        #pragma unroll
        for (int k = 0; k < NCHUNK / 32; k++) t += swsum[k];
        s_total = t;
    }
    __syncthreads();

    // ---- P7: store (tail implicitly zero) --------------------------------
    {
        const int total = s_total;                      // valid range [0, total)
        float4* o4 = (float4*)(out + base);
        const float4* s4 = (const float4*)outrow;
        #pragma unroll
        for (int i = tid; i < SS / 4; i += NT) {
            int e0 = i * 4;
            float4 v;
            if (e0 + 3 < total) {
                v = s4[i];
            } else if (e0 >= total) {
                v = make_float4(0.0f, 0.0f, 0.0f, 0.0f);
            } else {
                v.x = (e0     < total) ? outrow[e0]     : 0.0f;
                v.y = (e0 + 1 < total) ? outrow[e0 + 1] : 0.0f;
                v.z = (e0 + 2 < total) ? outrow[e0 + 2] : 0.0f;
                v.w = (e0 + 3 < total) ? outrow[e0 + 3] : 0.0f;
            }
            o4[i] = v;
        }
    }
}

extern "C" void kernel_launch(void* const* d_in, const int* in_sizes, int n_in,
                              void* d_out, int out_size)
{
    const float* x   = (const float*)d_in[0];
    const float* dly = (const float*)d_in[1];
    const float* rtt = (const float*)d_in[2];
    float* out = (float*)d_out;

    int B = in_sizes[0] / SS;
    traffic_kernel<<<B, NT>>>(x, dly, rtt, out);
}

// round 6
// speedup vs baseline: 1.4141x; 1.4141x over previous
#include <cuda_runtime.h>
#include <cuda_bf16.h>

// TrafficAugmentation [B=2048, S=4096] -> [B, S, 1] f32.
//
// Per row (one block, NT=256):
//  P0: stage x, dly into SMEM (float4).
//  P1: per-position delay countdown, 2 interleaved walks per thread
//      (exact sequential fsub chain) -> snxt[s] (u16 burst-end | kill).
//  P2: per 32-chunk exit table via warp-shfl pointer doubling (5 steps,
//      no LDS dependence; all 8 warps; aliases dead dly buffer).
//  P3: serial top walk (<=128 hops) -> chain entry per chunk.
//  P4: per-chunk output-slot counts; caches (nf, rem) per burst in a
//      thread-local array so P6 never recomputes sums/divisions.
//  P5: warp-shfl exclusive scan of chunk counts.
//  P6: pure emission of cached bursts at scanned offsets (dense, disjoint).
//  P7: store outrow[i] for i < total, else 0 (burst ranges tile [0,total)).

#define SS     4096
#define CHUNK  32
#define NCHUNK (SS / CHUNK)     // 128
#define MSSF   1448.0f
#define KILL16 0x8000u
#define NT     256

// Exact index-ordered sum of sx[s0..e1) via aligned float4 loads;
// fp op order identical to the scalar loop (predicated edges).
__device__ __forceinline__ float burst_sum(const float* __restrict__ sxp,
                                           int s0, int e1)
{
    const float4* v4 = (const float4*)sxp;
    float buf = 0.0f;
    for (int jb = (s0 & ~3); jb < e1; jb += 4) {
        float4 v = v4[jb >> 2];
        if (jb     >= s0)                 buf = __fadd_rn(buf, v.x);
        if (jb + 1 >= s0 && jb + 1 < e1)  buf = __fadd_rn(buf, v.y);
        if (jb + 2 >= s0 && jb + 2 < e1)  buf = __fadd_rn(buf, v.z);
        if (jb + 3 >= s0 && jb + 3 < e1)  buf = __fadd_rn(buf, v.w);
    }
    return buf;
}

__global__ __launch_bounds__(NT, 5)
void traffic_kernel(const float* __restrict__ x,
                    const float* __restrict__ dly,
                    const float* __restrict__ rtt,
                    float* __restrict__ out)
{
    __shared__ __align__(16) float sx[SS + 4];   // x row + 0 pads
    __shared__ __align__(16) float sd[SS + 4];   // dly row + 1e30 pads; later:
                                                 //  P2/P3: exit table (u16)
                                                 //  P6/P7: output row (f32)
    __shared__ unsigned short snxt[SS];          // burst-end | kill
    __shared__ unsigned short senter[NCHUNK];    // chain entry per chunk
    __shared__ int swsum[NCHUNK / 32];           // per-warp count totals
    __shared__ int s_total;                      // grand output count

    const int row  = blockIdx.x;
    const size_t base = (size_t)row * SS;
    const int tid = threadIdx.x;

    // ---- P0: stage inputs ------------------------------------------------
    {
        const float4* x4 = (const float4*)(x + base);
        const float4* d4 = (const float4*)(dly + base);
        float4* sx4 = (float4*)sx;
        float4* sd4 = (float4*)sd;
        #pragma unroll
        for (int i = tid; i < SS / 4; i += NT) { sx4[i] = x4[i]; sd4[i] = d4[i]; }
        if (tid < 4) { sx[SS + tid] = 0.0f; sd[SS + tid] = 1e30f; }
    }
    __syncthreads();

    // ---- P1: burst ends, two interleaved walks per thread ----------------
    #pragma unroll 1
    for (int k = 0; k < SS / NT; k += 2) {
        const int sA = tid + k * NT;
        const int sB = sA + NT;
        float rA = __ldg(rtt + base + sA);       // issue both early (MLP)
        float rB = __ldg(rtt + base + sB);
        const bool aliveA = (sx[sA] > 0.0f);
        const bool aliveB = (sx[sB] > 0.0f);
        int jA = sA, jB = sB;
        int endA = SS, endB = SS;
        bool runA = aliveA, runB = aliveB;
        while (runA || runB) {
            float a0, a1, a2, a3, b0, b1, b2, b3;
            if (runA) { a0 = sd[jA]; a1 = sd[jA+1]; a2 = sd[jA+2]; a3 = sd[jA+3]; }
            if (runB) { b0 = sd[jB]; b1 = sd[jB+1]; b2 = sd[jB+2]; b3 = sd[jB+3]; }
            if (runA) {                           // exact sequential chain (A)
                rA = __fsub_rn(rA, a0);
                if (rA <= 0.0f) { endA = jA + 1; runA = false; }
                else { rA = __fsub_rn(rA, a1);
                if (rA <= 0.0f) { endA = jA + 2; runA = false; }
                else { rA = __fsub_rn(rA, a2);
                if (rA <= 0.0f) { endA = jA + 3; runA = false; }
                else { rA = __fsub_rn(rA, a3); jA += 4;
                if (rA <= 0.0f) { endA = jA;     runA = false; } } } }
            }
            if (runB) {                           // exact sequential chain (B)
                rB = __fsub_rn(rB, b0);
                if (rB <= 0.0f) { endB = jB + 1; runB = false; }
                else { rB = __fsub_rn(rB, b1);
                if (rB <= 0.0f) { endB = jB + 2; runB = false; }
                else { rB = __fsub_rn(rB, b2);
                if (rB <= 0.0f) { endB = jB + 3; runB = false; }
                else { rB = __fsub_rn(rB, b3); jB += 4;
                if (rB <= 0.0f) { endB = jB;     runB = false; } } } }
            }
            // 1e30 pads at sd[SS..] force termination just past SS
        }
        snxt[sA] = aliveA ? (unsigned short)(endA < SS ? endA : SS)
                          : (unsigned short)KILL16;
        snxt[sB] = aliveB ? (unsigned short)(endB < SS ? endB : SS)
                          : (unsigned short)KILL16;
    }
    __syncthreads();

    // ---- P2: exit table via warp-shfl pointer doubling -------------------
    unsigned short* sexit = (unsigned short*)sd;       // dly is dead
    {
        const int wid  = tid >> 5;
        const int lane = tid & 31;
        for (int c = wid; c < NCHUNK; c += NT / 32) {  // 16 chunks per warp
            const int cbase = c * CHUNK;
            const int cend  = cbase + CHUNK;
            unsigned short w = snxt[cbase + lane];
            int E = (w & KILL16) ? SS : (int)w;        // kill -> chain dies
            #pragma unroll
            for (int step = 0; step < 5; step++) {     // 2^5 >= CHUNK
                int val = __shfl_sync(0xffffffffu, E, E & 31);
                E = (E < cend) ? val : E;              // E >= cbase always
            }
            sexit[cbase + lane] = (unsigned short)E;
        }
    }
    __syncthreads();

    // ---- P3: serial top walk (<= NCHUNK hops, branchy) -------------------
    if (tid == 0) {
        int pos = 0;
        #pragma unroll 4
        for (int c = 0; c < NCHUNK; c++) {
            senter[c] = (unsigned short)pos;
            if (pos < (c + 1) * CHUNK) pos = sexit[pos];
        }
    }
    __syncthreads();

    // ---- P4: per-chunk counts + per-burst (nf, rem) cache ----------------
    unsigned long long lburst[CHUNK];            // local mem, seq push/pop
    int cnt = 0, nb = 0;
    if (tid < NCHUNK) {
        const int end = (tid + 1) * CHUNK;
        int s = senter[tid];
        while (s < end) {
            unsigned short w = snxt[s];
            if (w & KILL16) break;
            const int e1 = (int)w;
            float buf = burst_sum(sx, s, e1);
            int nf = (int)ceilf(__fdiv_rn(buf, MSSF)) - 1;
            if (nf < 0) nf = 0;
            float rem = __fsub_rn(buf, __fmul_rn((float)nf, MSSF));
            cnt += nf + (rem > 0.0f ? 1 : 0);
            lburst[nb++] = ((unsigned long long)__float_as_uint(rem) << 32)
                         | (unsigned int)nf;
            s = e1;
        }
    }
    __syncthreads();   // sexit dead after this point; sd becomes outrow

    // ---- P5: warp-shfl exclusive scan of chunk counts --------------------
    int inc = cnt;
    if (tid < NCHUNK) {
        const int lane = tid & 31;
        #pragma unroll
        for (int d = 1; d < 32; d <<= 1) {
            int n = __shfl_up_sync(0xffffffffu, inc, d);
            if (lane >= d) inc += n;
        }
        if (lane == 31) swsum[tid >> 5] = inc;          // warp inclusive total
    }
    __syncthreads();

    // ---- P6: pure emission of cached bursts + grand total ----------------
    float* outrow = sd;
    if (tid < NCHUNK) {
        int o = inc - cnt;                              // exclusive within warp
        #pragma unroll
        for (int k = 0; k < NCHUNK / 32; k++)
            if (k < (tid >> 5)) o += swsum[k];
        for (int i = 0; i < nb; i++) {
            unsigned long long v = lburst[i];
            int nf    = (int)(unsigned int)(v & 0xFFFFFFFFu);
            float rem = __uint_as_float((unsigned int)(v >> 32));
            int lim = nf;
            if (o + lim > SS) lim = SS - o;             // truncation (may be <=0)
            for (int k = 0; k < lim; k++) outrow[o + k] = MSSF;
            if (rem > 0.0f && o + nf < SS) outrow[o + nf] = rem;
            o += nf + (rem > 0.0f ? 1 : 0);             // slots [o,o+cnt) dense
        }
    } else if (tid == NCHUNK) {
        int t = 0;
        #pragma unroll
        for (int k = 0; k < NCHUNK / 32; k++) t += swsum[k];
        s_total = (t < SS) ? t : SS;
    }
    __syncthreads();

    // ---- P7: store (tail implicitly zero) --------------------------------
    {
        const int total = s_total;                      // valid range [0, total)
        float4* o4 = (float4*)(out + base);
        const float4* s4 = (const float4*)outrow;
        #pragma unroll
        for (int i = tid; i < SS / 4; i += NT) {
            int e0 = i * 4;
            float4 v;
            if (e0 + 3 < total) {
                v = s4[i];
            } else if (e0 >= total) {
                v = make_float4(0.0f, 0.0f, 0.0f, 0.0f);
            } else {
                v.x = (e0     < total) ? outrow[e0]     : 0.0f;
                v.y = (e0 + 1 < total) ? outrow[e0 + 1] : 0.0f;
                v.z = (e0 + 2 < total) ? outrow[e0 + 2] : 0.0f;
                v.w = (e0 + 3 < total) ? outrow[e0 + 3] : 0.0f;
            }
            o4[i] = v;
        }
    }
}

extern "C" void kernel_launch(void* const* d_in, const int* in_sizes, int n_in,
                              void* d_out, int out_size)
{
    const float* x   = (const float*)d_in[0];
    const float* dly = (const float*)d_in[1];
    const float* rtt = (const float*)d_in[2];
    float* out = (float*)d_out;

    int B = in_sizes[0] / SS;
    traffic_kernel<<<B, NT>>>(x, dly, rtt, out);
}